// round 4
// baseline (speedup 1.0000x reference)
#include <cuda_runtime.h>
#include <cuda_bf16.h>
#include <cstdint>

// Problem constants
#define M_TOT 4608       // 2 * 2304 rows
#define CDIM  1280
#define SEQ   2304
#define HEADS 20
#define HD    64
#define QTILES 36        // 2304 / 64
#define KTILES 36

// ---------------- scratch (no allocation allowed) ----------------
__device__ float g_Q[(size_t)2 * HEADS * SEQ * HD];   // [b,h,s,d]
__device__ float g_K[(size_t)2 * HEADS * SEQ * HD];
__device__ float g_V[(size_t)2 * HEADS * SEQ * HD];
__device__ float g_att[(size_t)M_TOT * CDIM];         // [b*2304+s, h*64+d]

// ---------------- SGEMM: C = alpha * A@B (+bias), A[M,K], B[K,N] row-major ----
// 128x128 tile, BK=8, 256 threads, 8x8 per-thread microtile,
// register prefetch + double-buffered smem (one barrier per K-slice).
#define BM 128
#define BN 128
#define BK 8

__global__ __launch_bounds__(256) void sgemm_kernel(
    const float* __restrict__ A, const float* __restrict__ B,
    float* __restrict__ Cdst, int M, int N, int K,
    float alpha, const float* __restrict__ bias, int headedOut)
{
    __shared__ float As[2][BK][BM];
    __shared__ float Bs[2][BK][BN];
    const int t  = threadIdx.x;
    const int tx = t & 15, ty = t >> 4;
    const int m0 = blockIdx.y * BM, n0 = blockIdx.x * BN;

    const int aRow = t >> 1;           // 0..127
    const int aCol = (t & 1) << 2;     // 0 or 4
    const int bRow = t >> 5;           // 0..7
    const int bCol = (t & 31) << 2;    // 0..124

    const float* aPtr = A + (size_t)(m0 + aRow) * K + aCol;
    const float* bPtr = B + (size_t)bRow * N + n0 + bCol;

    float acc[8][8];
#pragma unroll
    for (int i = 0; i < 8; i++)
#pragma unroll
        for (int j = 0; j < 8; j++) acc[i][j] = 0.f;

    // prologue: fetch slice 0, commit to buffer 0
    float4 a4 = *reinterpret_cast<const float4*>(aPtr);
    float4 b4 = *reinterpret_cast<const float4*>(bPtr);
    As[0][aCol + 0][aRow] = a4.x;
    As[0][aCol + 1][aRow] = a4.y;
    As[0][aCol + 2][aRow] = a4.z;
    As[0][aCol + 3][aRow] = a4.w;
    *reinterpret_cast<float4*>(&Bs[0][bRow][bCol]) = b4;
    __syncthreads();

    const int nIter = K / BK;          // 160
    int cur = 0;
    for (int it = 0; it < nIter; it++) {
        const bool hasNext = (it + 1) < nIter;
        // issue next-slice global loads early (overlap with FFMA block)
        if (hasNext) {
            const int kNext = (it + 1) * BK;
            a4 = *reinterpret_cast<const float4*>(aPtr + kNext);
            b4 = *reinterpret_cast<const float4*>(bPtr + (size_t)kNext * N);
        }

#pragma unroll
        for (int kk = 0; kk < BK; kk++) {
            float a[8], b[8];
            *reinterpret_cast<float4*>(a)     = *reinterpret_cast<const float4*>(&As[cur][kk][ty * 8]);
            *reinterpret_cast<float4*>(a + 4) = *reinterpret_cast<const float4*>(&As[cur][kk][ty * 8 + 4]);
            *reinterpret_cast<float4*>(b)     = *reinterpret_cast<const float4*>(&Bs[cur][kk][tx * 8]);
            *reinterpret_cast<float4*>(b + 4) = *reinterpret_cast<const float4*>(&Bs[cur][kk][tx * 8 + 4]);
#pragma unroll
            for (int i = 0; i < 8; i++)
#pragma unroll
                for (int j = 0; j < 8; j++)
                    acc[i][j] = fmaf(a[i], b[j], acc[i][j]);
        }

        if (hasNext) {
            const int nxt = cur ^ 1;
            As[nxt][aCol + 0][aRow] = a4.x;
            As[nxt][aCol + 1][aRow] = a4.y;
            As[nxt][aCol + 2][aRow] = a4.z;
            As[nxt][aCol + 3][aRow] = a4.w;
            *reinterpret_cast<float4*>(&Bs[nxt][bRow][bCol]) = b4;
            __syncthreads();           // next buffer ready; also fences reuse of cur
            cur = nxt;
        }
    }

#pragma unroll
    for (int i = 0; i < 8; i++) {
        const int m = m0 + ty * 8 + i;
#pragma unroll
        for (int j = 0; j < 8; j++) {
            const int n = n0 + tx * 8 + j;
            float v = acc[i][j] * alpha;
            if (bias) v += bias[n];
            if (!headedOut) {
                Cdst[(size_t)m * N + n] = v;
            } else {
                // write into [b, h, s, d] for attention
                const int b = m / SEQ, s = m % SEQ;
                const int h = n >> 6, d = n & 63;
                Cdst[(((size_t)b * HEADS + h) * SEQ + s) * HD + d] = v;
            }
        }
    }
}

// ---------------- fused masked attention (flash style, fp32) ----------------
// grid: (36 q-tiles, 40 b*h), block 256. smem layout (dynamic):
//   Qt [64][64]  transposed: Qt[d*64 + i]
//   Kt [64][64]  transposed: Kt[d*64 + j]
//   Vs [64][64]  natural:    Vs[j*64 + d]
//   Pt [64][68]  transposed: Pt[j*68 + i]
//   Mb [64*64]   mask bytes
#define ATTN_SMEM_BYTES ((3 * 64 * 64 + 64 * 68) * 4 + 64 * 64)

__global__ __launch_bounds__(256) void attn_kernel(
    const float* __restrict__ Q, const float* __restrict__ K,
    const float* __restrict__ V, const int* __restrict__ mask,
    float* __restrict__ out)
{
    extern __shared__ float sm[];
    float* Qt = sm;
    float* Kt = Qt + 64 * 64;
    float* Vs = Kt + 64 * 64;
    float* Pt = Vs + 64 * 64;
    unsigned char* Mb = reinterpret_cast<unsigned char*>(Pt + 64 * 68);

    const int t  = threadIdx.x;
    const int tx = t & 15, ty = t >> 4;
    const int qt = blockIdx.x;
    const int bh = blockIdx.y;
    const int qrow0 = qt * 64;

    // ---- load Q tile transposed ----
    {
        const float* Qg = Q + ((size_t)bh * SEQ + qrow0) * HD;
        const int i  = t >> 2;
        const int d0 = (t & 3) << 4;
#pragma unroll
        for (int c = 0; c < 16; c += 4) {
            float4 v4 = *reinterpret_cast<const float4*>(Qg + (size_t)i * HD + d0 + c);
            Qt[(d0 + c + 0) * 64 + i] = v4.x;
            Qt[(d0 + c + 1) * 64 + i] = v4.y;
            Qt[(d0 + c + 2) * 64 + i] = v4.z;
            Qt[(d0 + c + 3) * 64 + i] = v4.w;
        }
    }

    float mrun[4], lrun[4], o[4][4];
#pragma unroll
    for (int i = 0; i < 4; i++) {
        mrun[i] = -1e30f; lrun[i] = 0.f;
#pragma unroll
        for (int j = 0; j < 4; j++) o[i][j] = 0.f;
    }

    for (int kt = 0; kt < KTILES; kt++) {
        __syncthreads();   // previous PV reads done before overwrite
        // ---- load K (transposed), V (natural), mask bytes ----
        {
            const float* Kg = K + ((size_t)bh * SEQ + kt * 64) * HD;
            const float* Vg = V + ((size_t)bh * SEQ + kt * 64) * HD;
            const int j  = t >> 2;
            const int d0 = (t & 3) << 4;
#pragma unroll
            for (int c = 0; c < 16; c += 4) {
                float4 v4 = *reinterpret_cast<const float4*>(Kg + (size_t)j * HD + d0 + c);
                Kt[(d0 + c + 0) * 64 + j] = v4.x;
                Kt[(d0 + c + 1) * 64 + j] = v4.y;
                Kt[(d0 + c + 2) * 64 + j] = v4.z;
                Kt[(d0 + c + 3) * 64 + j] = v4.w;
                *reinterpret_cast<float4*>(&Vs[(size_t)j * 64 + d0 + c]) =
                    *reinterpret_cast<const float4*>(Vg + (size_t)j * HD + d0 + c);
            }
            // mask rows qrow0+r, cols kt*64 .. +63 ; nonzero word == True
            const int r  = t >> 2;
            const int c0 = (t & 3) << 4;
            const int* mg = mask + (size_t)(qrow0 + r) * SEQ + kt * 64 + c0;
#pragma unroll
            for (int c = 0; c < 16; c += 4) {
                int4 mm = *reinterpret_cast<const int4*>(mg + c);
                Mb[r * 64 + c0 + c + 0] = (unsigned char)(mm.x != 0);
                Mb[r * 64 + c0 + c + 1] = (unsigned char)(mm.y != 0);
                Mb[r * 64 + c0 + c + 2] = (unsigned char)(mm.z != 0);
                Mb[r * 64 + c0 + c + 3] = (unsigned char)(mm.w != 0);
            }
        }
        __syncthreads();

        // ---- S = Q K^T (scale already folded into Q) ----
        float s[4][4];
#pragma unroll
        for (int i = 0; i < 4; i++)
#pragma unroll
            for (int j = 0; j < 4; j++) s[i][j] = 0.f;

#pragma unroll 8
        for (int d = 0; d < 64; d++) {
            float4 q4 = *reinterpret_cast<const float4*>(&Qt[d * 64 + ty * 4]);
            float4 k4 = *reinterpret_cast<const float4*>(&Kt[d * 64 + tx * 4]);
            const float qa[4] = {q4.x, q4.y, q4.z, q4.w};
            const float ka[4] = {k4.x, k4.y, k4.z, k4.w};
#pragma unroll
            for (int ii = 0; ii < 4; ii++)
#pragma unroll
                for (int jj = 0; jj < 4; jj++)
                    s[ii][jj] = fmaf(qa[ii], ka[jj], s[ii][jj]);
        }

        // ---- mask ----
#pragma unroll
        for (int ii = 0; ii < 4; ii++)
#pragma unroll
            for (int jj = 0; jj < 4; jj++)
                if (!Mb[(ty * 4 + ii) * 64 + tx * 4 + jj]) s[ii][jj] = -1e30f;

        // ---- online softmax (row reduce over 16 lanes sharing ty) ----
        float p[4][4];
#pragma unroll
        for (int ii = 0; ii < 4; ii++) {
            float mx = fmaxf(fmaxf(s[ii][0], s[ii][1]), fmaxf(s[ii][2], s[ii][3]));
            mx = fmaxf(mx, __shfl_xor_sync(0xffffffffu, mx, 1));
            mx = fmaxf(mx, __shfl_xor_sync(0xffffffffu, mx, 2));
            mx = fmaxf(mx, __shfl_xor_sync(0xffffffffu, mx, 4));
            mx = fmaxf(mx, __shfl_xor_sync(0xffffffffu, mx, 8));
            const float mnew = fmaxf(mrun[ii], mx);
            const float corr = __expf(mrun[ii] - mnew);
            mrun[ii] = mnew;
            float rs = 0.f;
#pragma unroll
            for (int jj = 0; jj < 4; jj++) {
                p[ii][jj] = __expf(s[ii][jj] - mnew);
                rs += p[ii][jj];
            }
            rs += __shfl_xor_sync(0xffffffffu, rs, 1);
            rs += __shfl_xor_sync(0xffffffffu, rs, 2);
            rs += __shfl_xor_sync(0xffffffffu, rs, 4);
            rs += __shfl_xor_sync(0xffffffffu, rs, 8);
            lrun[ii] = lrun[ii] * corr + rs;
#pragma unroll
            for (int dd = 0; dd < 4; dd++) o[ii][dd] *= corr;
        }

        // ---- store P transposed: Pt[j*68 + i] ----
#pragma unroll
        for (int jj = 0; jj < 4; jj++) {
            *reinterpret_cast<float4*>(&Pt[(tx * 4 + jj) * 68 + ty * 4]) =
                make_float4(p[0][jj], p[1][jj], p[2][jj], p[3][jj]);
        }
        __syncthreads();

        // ---- O += P V ----
#pragma unroll 8
        for (int j = 0; j < 64; j++) {
            float4 p4 = *reinterpret_cast<const float4*>(&Pt[j * 68 + ty * 4]);
            float4 v4 = *reinterpret_cast<const float4*>(&Vs[j * 64 + tx * 4]);
            const float pa[4] = {p4.x, p4.y, p4.z, p4.w};
            const float va[4] = {v4.x, v4.y, v4.z, v4.w};
#pragma unroll
            for (int ii = 0; ii < 4; ii++)
#pragma unroll
                for (int dd = 0; dd < 4; dd++)
                    o[ii][dd] = fmaf(pa[ii], va[dd], o[ii][dd]);
        }
    }

    // ---- finalize: out[b*2304+s, h*64+d] ----
    const int b = bh / HEADS, h = bh % HEADS;
#pragma unroll
    for (int ii = 0; ii < 4; ii++) {
        const float inv = 1.f / lrun[ii];
        const size_t m = (size_t)b * SEQ + qrow0 + ty * 4 + ii;
        *reinterpret_cast<float4*>(&out[m * CDIM + h * HD + tx * 4]) =
            make_float4(o[ii][0] * inv, o[ii][1] * inv, o[ii][2] * inv, o[ii][3] * inv);
    }
}

// ---------------- launch ----------------
extern "C" void kernel_launch(void* const* d_in, const int* in_sizes, int n_in,
                              void* d_out, int out_size)
{
    const float* hs  = (const float*)d_in[0];
    const int*   msk = (const int*)d_in[1];   // bool mask; nonzero word == True
    const float* Wq  = (const float*)d_in[2];
    const float* Wk  = (const float*)d_in[3];
    const float* Wv  = (const float*)d_in[4];
    const float* Wo  = (const float*)d_in[5];
    const float* bo  = (const float*)d_in[6];
    float* out = (float*)d_out;

    float *Qp, *Kp, *Vp, *Ap;
    cudaGetSymbolAddress((void**)&Qp, g_Q);
    cudaGetSymbolAddress((void**)&Kp, g_K);
    cudaGetSymbolAddress((void**)&Vp, g_V);
    cudaGetSymbolAddress((void**)&Ap, g_att);

    const dim3 gblk(CDIM / BN, M_TOT / BM);   // (10, 36)

    // Q/K/V projections, writing [b,h,s,d]; 1/sqrt(64) folded into Q
    sgemm_kernel<<<gblk, 256>>>(hs, Wq, Qp, M_TOT, CDIM, CDIM, 0.125f, nullptr, 1);
    sgemm_kernel<<<gblk, 256>>>(hs, Wk, Kp, M_TOT, CDIM, CDIM, 1.0f,   nullptr, 1);
    sgemm_kernel<<<gblk, 256>>>(hs, Wv, Vp, M_TOT, CDIM, CDIM, 1.0f,   nullptr, 1);

    cudaFuncSetAttribute(attn_kernel, cudaFuncAttributeMaxDynamicSharedMemorySize,
                         ATTN_SMEM_BYTES);
    attn_kernel<<<dim3(QTILES, 2 * HEADS), 256, ATTN_SMEM_BYTES>>>(Qp, Kp, Vp, msk, Ap);

    // output projection + bias, straight into d_out
    sgemm_kernel<<<gblk, 256>>>(Ap, Wo, out, M_TOT, CDIM, CDIM, 1.0f, bo, 0);
}

// round 7
// speedup vs baseline: 1.2137x; 1.2137x over previous
#include <cuda_runtime.h>
#include <cuda_bf16.h>
#include <mma.h>
#include <cstdint>

using namespace nvcuda;

// Problem constants
#define M_TOT 4608       // 2 * 2304 rows
#define CDIM  1280
#define SEQ   2304
#define HEADS 20
#define HD    64
#define QTILES 36
#define KTILES 36

// ---------------- scratch (no allocation allowed) ----------------
__device__ float g_Q[(size_t)2 * HEADS * SEQ * HD];   // [b,h,s,d]
__device__ float g_K[(size_t)2 * HEADS * SEQ * HD];
__device__ float g_V[(size_t)2 * HEADS * SEQ * HD];
__device__ float g_att[(size_t)M_TOT * CDIM];         // [b*2304+s, h*64+d]
__device__ float g_Wt[4][(size_t)CDIM * CDIM];        // transposed weights [n][k]

// ---------------- weight transpose: Wt[n][k] = W[k][n] ----------------
__global__ __launch_bounds__(256) void transpose_w(
    const float* __restrict__ Wq, const float* __restrict__ Wk,
    const float* __restrict__ Wv, const float* __restrict__ Wo)
{
    __shared__ float tile[32][33];
    const float* W = (blockIdx.z == 0) ? Wq : (blockIdx.z == 1) ? Wk
                   : (blockIdx.z == 2) ? Wv : Wo;
    float* Wt = g_Wt[blockIdx.z];
    const int k0 = blockIdx.x * 32, n0 = blockIdx.y * 32;
    const int tx = threadIdx.x, ty = threadIdx.y;  // 32 x 8
#pragma unroll
    for (int i = 0; i < 4; i++)
        tile[ty + 8 * i][tx] = W[(size_t)(k0 + ty + 8 * i) * CDIM + n0 + tx];
    __syncthreads();
#pragma unroll
    for (int i = 0; i < 4; i++)
        Wt[(size_t)(n0 + ty + 8 * i) * CDIM + k0 + tx] = tile[tx][ty + 8 * i];
}

// ---------------- wmma tf32 GEMM: C[m][n] = alpha*sum_k A[m][k]*Bt[n][k] (+bias) ----
// 128x128 block tile, 8 warps (4 m x 2 n), warp tile 32x64, BK=32.
#define GBK 32
#define GST 36   // smem row stride (floats)

__global__ __launch_bounds__(256) void gemm_wmma(
    const float* __restrict__ A, const float* __restrict__ Bt,
    float* __restrict__ C, float alpha, const float* __restrict__ bias, int headedOut)
{
    __shared__ float As[128 * GST];
    __shared__ float Bs[128 * GST];
    __shared__ float biasS[16 * 132];

    const int t = threadIdx.x;
    const int wid = t >> 5;
    const int m0 = blockIdx.y * 128, n0 = blockIdx.x * 128;
    const int wm = (wid & 3) * 32;    // warp m offset
    const int wn = (wid >> 2) * 64;   // warp n offset

    wmma::fragment<wmma::accumulator, 16, 16, 8, float> acc[2][4];
    if (bias) {
        for (int i = t; i < 16 * 128; i += 256)
            biasS[(i >> 7) * 132 + (i & 127)] = bias[n0 + (i & 127)];
        __syncthreads();
#pragma unroll
        for (int im = 0; im < 2; im++)
#pragma unroll
            for (int in = 0; in < 4; in++)
                wmma::load_matrix_sync(acc[im][in], &biasS[wn + in * 16], 132,
                                       wmma::mem_row_major);
    } else {
#pragma unroll
        for (int im = 0; im < 2; im++)
#pragma unroll
            for (int in = 0; in < 4; in++)
                wmma::fill_fragment(acc[im][in], 0.f);
    }

    // each thread loads 16 floats of A and 16 of B per K-slice
    const int row  = t >> 1;           // 0..127
    const int half = (t & 1) * 16;     // 0 or 16
    const float* aPtr = A  + (size_t)(m0 + row) * CDIM + half;
    const float* bPtr = Bt + (size_t)(n0 + row) * CDIM + half;

    float4 pa[4], pb[4];
#pragma unroll
    for (int c = 0; c < 4; c++) {
        pa[c] = *reinterpret_cast<const float4*>(aPtr + 4 * c);
        pb[c] = *reinterpret_cast<const float4*>(bPtr + 4 * c);
    }

    const int nIter = CDIM / GBK;      // 40
#pragma unroll 1
    for (int it = 0; it < nIter; it++) {
        // commit current slice (alpha folded into A)
#pragma unroll
        for (int c = 0; c < 4; c++) {
            *reinterpret_cast<float4*>(&As[row * GST + half + 4 * c]) =
                make_float4(pa[c].x * alpha, pa[c].y * alpha, pa[c].z * alpha, pa[c].w * alpha);
            *reinterpret_cast<float4*>(&Bs[row * GST + half + 4 * c]) = pb[c];
        }
        __syncthreads();

        // prefetch next slice
        if (it + 1 < nIter) {
            const int kN = (it + 1) * GBK;
#pragma unroll
            for (int c = 0; c < 4; c++) {
                pa[c] = *reinterpret_cast<const float4*>(aPtr + kN + 4 * c);
                pb[c] = *reinterpret_cast<const float4*>(bPtr + kN + 4 * c);
            }
        }

#pragma unroll
        for (int ks = 0; ks < 4; ks++) {
            wmma::fragment<wmma::matrix_a, 16, 16, 8, wmma::precision::tf32, wmma::row_major> af[2];
            wmma::fragment<wmma::matrix_b, 16, 16, 8, wmma::precision::tf32, wmma::col_major> bf[4];
#pragma unroll
            for (int im = 0; im < 2; im++) {
                wmma::load_matrix_sync(af[im], &As[(wm + im * 16) * GST + ks * 8], GST);
#pragma unroll
                for (int e = 0; e < af[im].num_elements; e++)
                    af[im].x[e] = wmma::__float_to_tf32(af[im].x[e]);
            }
#pragma unroll
            for (int in = 0; in < 4; in++) {
                wmma::load_matrix_sync(bf[in], &Bs[(wn + in * 16) * GST + ks * 8], GST);
#pragma unroll
                for (int e = 0; e < bf[in].num_elements; e++)
                    bf[in].x[e] = wmma::__float_to_tf32(bf[in].x[e]);
            }
#pragma unroll
            for (int im = 0; im < 2; im++)
#pragma unroll
                for (int in = 0; in < 4; in++)
                    wmma::mma_sync(acc[im][in], af[im], bf[in], acc[im][in]);
        }
        __syncthreads();
    }

    // ---- store: fragments straight to gmem ----
#pragma unroll
    for (int im = 0; im < 2; im++) {
        const int m = m0 + wm + im * 16;
#pragma unroll
        for (int in = 0; in < 4; in++) {
            const int n = n0 + wn + in * 16;
            if (!headedOut) {
                wmma::store_matrix_sync(C + (size_t)m * CDIM + n, acc[im][in], CDIM,
                                        wmma::mem_row_major);
            } else {
                // [b, h, s, d]; a 16-wide fragment never crosses a head boundary
                const int b = m / SEQ, s = m % SEQ, h = n >> 6, d0 = n & 63;
                wmma::store_matrix_sync(
                    C + (((size_t)b * HEADS + h) * SEQ + s) * HD + d0,
                    acc[im][in], HD, wmma::mem_row_major);
            }
        }
    }
}

// ---------------- fused masked attention (flash style, fp32) ----------------
#define ATTN_SMEM_BYTES ((3 * 64 * 64 + 64 * 68) * 4 + 64 * 64)

__global__ __launch_bounds__(256) void attn_kernel(
    const float* __restrict__ Q, const float* __restrict__ K,
    const float* __restrict__ V, const int* __restrict__ mask,
    float* __restrict__ out)
{
    extern __shared__ float sm[];
    float* Qt = sm;
    float* Kt = Qt + 64 * 64;
    float* Vs = Kt + 64 * 64;
    float* Pt = Vs + 64 * 64;
    unsigned char* Mb = reinterpret_cast<unsigned char*>(Pt + 64 * 68);

    const int t  = threadIdx.x;
    const int tx = t & 15, ty = t >> 4;
    const int qt = blockIdx.x;
    const int bh = blockIdx.y;
    const int qrow0 = qt * 64;

    {
        const float* Qg = Q + ((size_t)bh * SEQ + qrow0) * HD;
        const int i  = t >> 2;
        const int d0 = (t & 3) << 4;
#pragma unroll
        for (int c = 0; c < 16; c += 4) {
            float4 v4 = *reinterpret_cast<const float4*>(Qg + (size_t)i * HD + d0 + c);
            Qt[(d0 + c + 0) * 64 + i] = v4.x;
            Qt[(d0 + c + 1) * 64 + i] = v4.y;
            Qt[(d0 + c + 2) * 64 + i] = v4.z;
            Qt[(d0 + c + 3) * 64 + i] = v4.w;
        }
    }

    float mrun[4], lrun[4], o[4][4];
#pragma unroll
    for (int i = 0; i < 4; i++) {
        mrun[i] = -1e30f; lrun[i] = 0.f;
#pragma unroll
        for (int j = 0; j < 4; j++) o[i][j] = 0.f;
    }

    for (int kt = 0; kt < KTILES; kt++) {
        __syncthreads();
        {
            const float* Kg = K + ((size_t)bh * SEQ + kt * 64) * HD;
            const float* Vg = V + ((size_t)bh * SEQ + kt * 64) * HD;
            const int j  = t >> 2;
            const int d0 = (t & 3) << 4;
#pragma unroll
            for (int c = 0; c < 16; c += 4) {
                float4 v4 = *reinterpret_cast<const float4*>(Kg + (size_t)j * HD + d0 + c);
                Kt[(d0 + c + 0) * 64 + j] = v4.x;
                Kt[(d0 + c + 1) * 64 + j] = v4.y;
                Kt[(d0 + c + 2) * 64 + j] = v4.z;
                Kt[(d0 + c + 3) * 64 + j] = v4.w;
                *reinterpret_cast<float4*>(&Vs[(size_t)j * 64 + d0 + c]) =
                    *reinterpret_cast<const float4*>(Vg + (size_t)j * HD + d0 + c);
            }
            const int r  = t >> 2;
            const int c0 = (t & 3) << 4;
            const int* mg = mask + (size_t)(qrow0 + r) * SEQ + kt * 64 + c0;
#pragma unroll
            for (int c = 0; c < 16; c += 4) {
                int4 mm = *reinterpret_cast<const int4*>(mg + c);
                Mb[r * 64 + c0 + c + 0] = (unsigned char)(mm.x != 0);
                Mb[r * 64 + c0 + c + 1] = (unsigned char)(mm.y != 0);
                Mb[r * 64 + c0 + c + 2] = (unsigned char)(mm.z != 0);
                Mb[r * 64 + c0 + c + 3] = (unsigned char)(mm.w != 0);
            }
        }
        __syncthreads();

        float s[4][4];
#pragma unroll
        for (int i = 0; i < 4; i++)
#pragma unroll
            for (int j = 0; j < 4; j++) s[i][j] = 0.f;

#pragma unroll 8
        for (int d = 0; d < 64; d++) {
            float4 q4 = *reinterpret_cast<const float4*>(&Qt[d * 64 + ty * 4]);
            float4 k4 = *reinterpret_cast<const float4*>(&Kt[d * 64 + tx * 4]);
            const float qa[4] = {q4.x, q4.y, q4.z, q4.w};
            const float ka[4] = {k4.x, k4.y, k4.z, k4.w};
#pragma unroll
            for (int ii = 0; ii < 4; ii++)
#pragma unroll
                for (int jj = 0; jj < 4; jj++)
                    s[ii][jj] = fmaf(qa[ii], ka[jj], s[ii][jj]);
        }

#pragma unroll
        for (int ii = 0; ii < 4; ii++)
#pragma unroll
            for (int jj = 0; jj < 4; jj++)
                if (!Mb[(ty * 4 + ii) * 64 + tx * 4 + jj]) s[ii][jj] = -1e30f;

        float p[4][4];
#pragma unroll
        for (int ii = 0; ii < 4; ii++) {
            float mx = fmaxf(fmaxf(s[ii][0], s[ii][1]), fmaxf(s[ii][2], s[ii][3]));
            mx = fmaxf(mx, __shfl_xor_sync(0xffffffffu, mx, 1));
            mx = fmaxf(mx, __shfl_xor_sync(0xffffffffu, mx, 2));
            mx = fmaxf(mx, __shfl_xor_sync(0xffffffffu, mx, 4));
            mx = fmaxf(mx, __shfl_xor_sync(0xffffffffu, mx, 8));
            const float mnew = fmaxf(mrun[ii], mx);
            const float corr = __expf(mrun[ii] - mnew);
            mrun[ii] = mnew;
            float rs = 0.f;
#pragma unroll
            for (int jj = 0; jj < 4; jj++) {
                p[ii][jj] = __expf(s[ii][jj] - mnew);
                rs += p[ii][jj];
            }
            rs += __shfl_xor_sync(0xffffffffu, rs, 1);
            rs += __shfl_xor_sync(0xffffffffu, rs, 2);
            rs += __shfl_xor_sync(0xffffffffu, rs, 4);
            rs += __shfl_xor_sync(0xffffffffu, rs, 8);
            lrun[ii] = lrun[ii] * corr + rs;
#pragma unroll
            for (int dd = 0; dd < 4; dd++) o[ii][dd] *= corr;
        }

#pragma unroll
        for (int jj = 0; jj < 4; jj++) {
            *reinterpret_cast<float4*>(&Pt[(tx * 4 + jj) * 68 + ty * 4]) =
                make_float4(p[0][jj], p[1][jj], p[2][jj], p[3][jj]);
        }
        __syncthreads();

#pragma unroll 8
        for (int j = 0; j < 64; j++) {
            float4 p4 = *reinterpret_cast<const float4*>(&Pt[j * 68 + ty * 4]);
            float4 v4 = *reinterpret_cast<const float4*>(&Vs[j * 64 + tx * 4]);
            const float pa[4] = {p4.x, p4.y, p4.z, p4.w};
            const float va[4] = {v4.x, v4.y, v4.z, v4.w};
#pragma unroll
            for (int ii = 0; ii < 4; ii++)
#pragma unroll
                for (int dd = 0; dd < 4; dd++)
                    o[ii][dd] = fmaf(pa[ii], va[dd], o[ii][dd]);
        }
    }

    const int b = bh / HEADS, h = bh % HEADS;
#pragma unroll
    for (int ii = 0; ii < 4; ii++) {
        const float inv = 1.f / lrun[ii];
        const size_t m = (size_t)b * SEQ + qrow0 + ty * 4 + ii;
        *reinterpret_cast<float4*>(&out[m * CDIM + h * HD + tx * 4]) =
            make_float4(o[ii][0] * inv, o[ii][1] * inv, o[ii][2] * inv, o[ii][3] * inv);
    }
}

// ---------------- launch ----------------
extern "C" void kernel_launch(void* const* d_in, const int* in_sizes, int n_in,
                              void* d_out, int out_size)
{
    const float* hs  = (const float*)d_in[0];
    const int*   msk = (const int*)d_in[1];
    const float* Wq  = (const float*)d_in[2];
    const float* Wk  = (const float*)d_in[3];
    const float* Wv  = (const float*)d_in[4];
    const float* Wo  = (const float*)d_in[5];
    const float* bo  = (const float*)d_in[6];
    float* out = (float*)d_out;

    float *Qp, *Kp, *Vp, *Ap, *Wtp;
    cudaGetSymbolAddress((void**)&Qp, g_Q);
    cudaGetSymbolAddress((void**)&Kp, g_K);
    cudaGetSymbolAddress((void**)&Vp, g_V);
    cudaGetSymbolAddress((void**)&Ap, g_att);
    cudaGetSymbolAddress((void**)&Wtp, g_Wt);
    const float* Wt0 = Wtp;
    const float* Wt1 = Wtp + (size_t)CDIM * CDIM;
    const float* Wt2 = Wtp + (size_t)2 * CDIM * CDIM;
    const float* Wt3 = Wtp + (size_t)3 * CDIM * CDIM;

    cudaFuncSetAttribute(attn_kernel, cudaFuncAttributeMaxDynamicSharedMemorySize, ATTN_SMEM_BYTES);

    // transpose the 4 weight matrices: Wt[n][k] = W[k][n]
    transpose_w<<<dim3(CDIM / 32, CDIM / 32, 4), dim3(32, 8)>>>(Wq, Wk, Wv, Wo);

    const dim3 gg(CDIM / 128, M_TOT / 128);   // (10, 36)
    // Q/K/V projections (tf32 wmma), writing [b,h,s,d]; 1/8 folded into Q
    gemm_wmma<<<gg, 256>>>(hs, Wt0, Qp, 0.125f, nullptr, 1);
    gemm_wmma<<<gg, 256>>>(hs, Wt1, Kp, 1.0f,   nullptr, 1);
    gemm_wmma<<<gg, 256>>>(hs, Wt2, Vp, 1.0f,   nullptr, 1);

    attn_kernel<<<dim3(QTILES, 2 * HEADS), 256, ATTN_SMEM_BYTES>>>(Qp, Kp, Vp, msk, Ap);

    // output projection + bias, straight into d_out
    gemm_wmma<<<gg, 256>>>(Ap, Wt3, out, 1.0f, bo, 0);
}